// round 9
// baseline (speedup 1.0000x reference)
#include <cuda_runtime.h>
#include <math.h>

#define EPSF 1e-5f
#define NBT 4
#define SPT_STR 256   // feature-major row stride (ND <= 256)

typedef unsigned long long ull;

// leaky_relu(z, 0.01) == 0.505*z + 0.495*|z|
__device__ __forceinline__ float lrelu(float z) {
    return fmaf(0.495f, fabsf(z), 0.505f * z);
}

// packed helpers (sm_103a f32x2 pipe)
#define FMA2(acc, a, b) \
    asm("fma.rn.f32x2 %0, %1, %2, %0;" : "+l"(acc) : "l"(a), "l"(b))
#define AND2(d, s, m) \
    asm("and.b64 %0, %1, %2;" : "=l"(d) : "l"(s), "l"(m))
#define PACK2(d, x) \
    asm("mov.b64 %0, {%1, %1};" : "=l"(d) : "r"(__float_as_uint(x)))
#define PACK2U(d, x) \
    asm("mov.b64 %0, {%1, %1};" : "=l"(d) : "r"(x))
#define UNPACK2(lo, hi, s) \
    asm("mov.b64 {%0, %1}, %2;" : "=r"(lo), "=r"(hi) : "l"(s))

__global__ __launch_bounds__(256) void netlocal_kernel(
    const float* __restrict__ x0g,   // [B,T,3]
    const float* __restrict__ xg,    // [B,T,ND,3]
    const int*   __restrict__ Ng,    // [B,T]
    const float* __restrict__ basisg,// [B,3,3]
    const float* __restrict__ vg,    // [B,T,ND,3]
    const float* __restrict__ Pg,    // [B]
    const float* __restrict__ W0,    // [19,127]
    const float* __restrict__ b0,    // [127]
    const float* __restrict__ W1,    // [128,128]
    const float* __restrict__ b1,    // [128]
    const float* __restrict__ W2,    // [128,128]
    const float* __restrict__ b2,    // [128]
    float*       __restrict__ outg,  // [B,T,128]
    int T, int ND, int BT)
{
    const int bt0 = blockIdx.x * NBT;
    const int tid = threadIdx.x;
    const int nq  = min(NBT, BT - bt0);

    __shared__ __align__(16) float spT[9 * SPT_STR];  // feature-major per-halo
    __shared__ float sbasis[9];
    __shared__ float fblk[10];
    __shared__ float sv0[3];
    __shared__ float wsum[8][3];
    __shared__ float poolp[128 * 5];                  // [col][slice]
    __shared__ __align__(16) float hbuf[128][NBT];    // pooled h, [k][bt]
    __shared__ __align__(16) float h1buf[128][NBT];
    __shared__ __align__(16) float pD[256][NBT];      // Phase-D partials

    // ---- hoisted Phase-C weights (bt-invariant): columns {j63, j63+64} ----
    const int j63 = tid & 63;
    const int s4  = tid >> 6;
    ull w2[2][9];
#pragma unroll
    for (int c = 0; c < 2; c++) {
        const int col = j63 + 64 * c;
        float wr[9];
        if (col < 127) {
            wr[0] = W0[0 * 127 + col];
            wr[1] = W0[1 * 127 + col];
            wr[2] = W0[2 * 127 + col];
            wr[3] = W0[3 * 127 + col];
            wr[4] = W0[14 * 127 + col];
            wr[5] = W0[15 * 127 + col];
            wr[6] = W0[16 * 127 + col];
            wr[7] = W0[17 * 127 + col];
            wr[8] = W0[18 * 127 + col];
        } else {
#pragma unroll
            for (int i = 0; i < 9; i++) wr[i] = 0.f;
        }
#pragma unroll
        for (int i = 0; i < 9; i++) PACK2(w2[c][i], wr[i]);
    }
    ull c505, c495, mabs;
    PACK2(c505, 0.505f);
    PACK2(c495, 0.495f);
    PACK2U(mabs, 0x7FFFFFFFu);

    for (int q = 0; q < nq; q++) {
        const int bt = bt0 + q;
        const int b  = bt / T;
        if (tid < 9) sbasis[tid] = basisg[b * 9 + tid];

        const float* vbase = vg + (size_t)bt * ND * 3;
        const float* xbase = xg + (size_t)bt * ND * 3;

        // ---- Phase A: v0 = mean over ND (deterministic tree reduction) ----
        float vx = 0.f, vy = 0.f, vz = 0.f;
        for (int n = tid; n < ND; n += 256) {
            vx += vbase[n * 3 + 0];
            vy += vbase[n * 3 + 1];
            vz += vbase[n * 3 + 2];
        }
#pragma unroll
        for (int o = 16; o > 0; o >>= 1) {
            vx += __shfl_xor_sync(0xffffffffu, vx, o);
            vy += __shfl_xor_sync(0xffffffffu, vy, o);
            vz += __shfl_xor_sync(0xffffffffu, vz, o);
        }
        if ((tid & 31) == 0) {
            wsum[tid >> 5][0] = vx;
            wsum[tid >> 5][1] = vy;
            wsum[tid >> 5][2] = vz;
        }
        __syncthreads();

        if (tid == 0) {
            float sx = 0.f, sy = 0.f, sz = 0.f;
#pragma unroll
            for (int w = 0; w < 8; w++) { sx += wsum[w][0]; sy += wsum[w][1]; sz += wsum[w][2]; }
            const float invN = 1.0f / (float)ND;
            const float v0x = sx * invN, v0y = sy * invN, v0z = sz * invN;
            sv0[0] = v0x; sv0[1] = v0y; sv0[2] = v0z;

            const float x00 = x0g[bt * 3 + 0], x01 = x0g[bt * 3 + 1], x02 = x0g[bt * 3 + 2];
            const float x0n = sqrtf(x00 * x00 + x01 * x01 + x02 * x02) + EPSF;
            const float ix  = 1.0f / x0n;
            const float x0ux = x00 * ix, x0uy = x01 * ix, x0uz = x02 * ix;

            const float v0n = sqrtf(v0x * v0x + v0y * v0y + v0z * v0z) + EPSF;
            const float iv  = 1.0f / v0n;
            const float v0ux = v0x * iv, v0uy = v0y * iv, v0uz = v0z * iv;

            fblk[0] = log1pf((float)Ng[bt]);                                   // f4
            fblk[1] = x0n;                                                     // f5
            fblk[2] = x0ux * sbasis[0] + x0uy * sbasis[1] + x0uz * sbasis[2];  // f6
            fblk[3] = x0ux * sbasis[3] + x0uy * sbasis[4] + x0uz * sbasis[5];  // f7
            fblk[4] = x0ux * sbasis[6] + x0uy * sbasis[7] + x0uz * sbasis[8];  // f8
            fblk[5] = v0n;                                                     // f9
            fblk[6] = v0ux * sbasis[0] + v0uy * sbasis[1] + v0uz * sbasis[2];  // f10
            fblk[7] = v0ux * sbasis[3] + v0uy * sbasis[4] + v0uz * sbasis[5];  // f11
            fblk[8] = v0ux * sbasis[6] + v0uy * sbasis[7] + v0uz * sbasis[8];  // f12
            fblk[9] = x0ux * v0ux + x0uy * v0uy + x0uz * v0uz;                 // f13
        }
        __syncthreads();

        // ---- Phase B: per-particle features (9) into feature-major shared ----
        {
            const float v0x = sv0[0], v0y = sv0[1], v0z = sv0[2];
            const float bx0 = sbasis[0], bx1 = sbasis[1], bx2 = sbasis[2];
            const float by0 = sbasis[3], by1 = sbasis[4], by2 = sbasis[5];
            const float bz0 = sbasis[6], bz1 = sbasis[7], bz2 = sbasis[8];
            for (int n = tid; n < ND; n += 256) {
                const float ax = xbase[n * 3 + 0], ay = xbase[n * 3 + 1], az = xbase[n * 3 + 2];
                const float xn = sqrtf(ax * ax + ay * ay + az * az) + EPSF;
                const float ir = 1.0f / xn;
                const float xux = ax * ir, xuy = ay * ir, xuz = az * ir;

                const float wx = vbase[n * 3 + 0] - v0x;
                const float wy = vbase[n * 3 + 1] - v0y;
                const float wz = vbase[n * 3 + 2] - v0z;
                const float vn = sqrtf(wx * wx + wy * wy + wz * wz) + EPSF;
                const float ivn = 1.0f / vn;
                const float vux = wx * ivn, vuy = wy * ivn, vuz = wz * ivn;

                spT[0 * SPT_STR + n] = xn;
                spT[1 * SPT_STR + n] = xux * bx0 + xuy * bx1 + xuz * bx2;
                spT[2 * SPT_STR + n] = xux * by0 + xuy * by1 + xuz * by2;
                spT[3 * SPT_STR + n] = xux * bz0 + xuy * bz1 + xuz * bz2;
                spT[4 * SPT_STR + n] = vn;
                spT[5 * SPT_STR + n] = vux * bx0 + vuy * bx1 + vuz * bx2;
                spT[6 * SPT_STR + n] = vux * by0 + vuy * by1 + vuz * by2;
                spT[7 * SPT_STR + n] = vux * bz0 + vuy * bz1 + vuz * bz2;
                spT[8 * SPT_STR + n] = xux * vux + xuy * vuy + xuz * vuz;
            }
        }
        __syncthreads();

        // ---- Phase C: MLP0 + mean pool, packed f32x2 ----
        {
            ull zc2[2];
#pragma unroll
            for (int c = 0; c < 2; c++) {
                const int col = j63 + 64 * c;
                float zv = 0.f;
                if (col < 127) {
                    zv = b0[col];
#pragma unroll
                    for (int i = 0; i < 10; i++)
                        zv = fmaf(fblk[i], W0[(4 + i) * 127 + col], zv);
                }
                PACK2(zc2[c], zv);
            }

            const int nspl = ND >> 2;       // particles per slice
            const int n0b  = s4 * nspl;
            ull acc[2][2] = {{0ull, 0ull}, {0ull, 0ull}};

            for (int i = 0; i < nspl; i += 4) {
                const int n0 = n0b + i;
                ull z00 = zc2[0], z01 = zc2[0], z10 = zc2[1], z11 = zc2[1];
#pragma unroll
                for (int k = 0; k < 9; k++) {
                    const ulonglong2 qv =
                        *(const ulonglong2*)(spT + k * SPT_STR + n0);
                    FMA2(z00, w2[0][k], qv.x);
                    FMA2(z01, w2[0][k], qv.y);
                    FMA2(z10, w2[1][k], qv.x);
                    FMA2(z11, w2[1][k], qv.y);
                }
                ull a;
                AND2(a, z00, mabs); FMA2(acc[0][0], c505, z00); FMA2(acc[0][0], c495, a);
                AND2(a, z01, mabs); FMA2(acc[0][1], c505, z01); FMA2(acc[0][1], c495, a);
                AND2(a, z10, mabs); FMA2(acc[1][0], c505, z10); FMA2(acc[1][0], c495, a);
                AND2(a, z11, mabs); FMA2(acc[1][1], c505, z11); FMA2(acc[1][1], c495, a);
            }

#pragma unroll
            for (int c = 0; c < 2; c++) {
                unsigned int l0, h0, l1, h1;
                UNPACK2(l0, h0, acc[c][0]);
                UNPACK2(l1, h1, acc[c][1]);
                const float tot = (__uint_as_float(l0) + __uint_as_float(h0)) +
                                  (__uint_as_float(l1) + __uint_as_float(h1));
                poolp[(j63 + 64 * c) * 5 + s4] = tot;
            }
        }
        __syncthreads();

        if (tid < 128) {
            float sm = 0.f;
#pragma unroll
            for (int w = 0; w < 4; w++) sm += poolp[tid * 5 + w];
            hbuf[tid][q] = (tid < 127) ? sm * (1.0f / (float)ND) : fblk[0];
        }
        __syncthreads();
    }

    // ---- Phase D: batched over NBT halos, f32x2-packed over halo pairs ----
    const int j = tid & 127;
    const int h = tid >> 7;
    {
        ull a01, a23;
        const float bv = (h == 0) ? b1[j] : 0.f;
        PACK2(a01, bv);
        PACK2(a23, bv);
        const int k0 = h * 64;
#pragma unroll 4
        for (int k = k0; k < k0 + 64; k++) {
            ull wv; PACK2(wv, W1[k * 128 + j]);
            FMA2(a01, wv, *(const ull*)&hbuf[k][0]);
            FMA2(a23, wv, *(const ull*)&hbuf[k][2]);
        }
        *(ull*)&pD[tid][0] = a01;
        *(ull*)&pD[tid][2] = a23;
    }
    __syncthreads();
    if (tid < 128) {
#pragma unroll
        for (int q = 0; q < NBT; q++)
            h1buf[tid][q] = lrelu(pD[tid][q] + pD[tid + 128][q]);
    }
    __syncthreads();
    {
        ull a01, a23;
        const float bv = (h == 0) ? b2[j] : 0.f;
        PACK2(a01, bv);
        PACK2(a23, bv);
        const int k0 = h * 64;
#pragma unroll 4
        for (int k = k0; k < k0 + 64; k++) {
            ull wv; PACK2(wv, W2[k * 128 + j]);
            FMA2(a01, wv, *(const ull*)&h1buf[k][0]);
            FMA2(a23, wv, *(const ull*)&h1buf[k][2]);
        }
        *(ull*)&pD[tid][0] = a01;
        *(ull*)&pD[tid][2] = a23;
    }
    __syncthreads();
    if (tid < 128) {
        for (int q = 0; q < nq; q++) {
            const int bt = bt0 + q;
            outg[(size_t)bt * 128 + tid] =
                (pD[tid][q] + pD[tid + 128][q]) * (1.0f / Pg[bt / T]);
        }
    }
}

extern "C" void kernel_launch(void* const* d_in, const int* in_sizes, int n_in,
                              void* d_out, int out_size) {
    const float* x0g    = (const float*)d_in[0];
    const float* xg     = (const float*)d_in[1];
    const int*   Ng     = (const int*)  d_in[2];
    const float* basisg = (const float*)d_in[3];
    const float* vg     = (const float*)d_in[4];
    const float* Pg     = (const float*)d_in[5];
    const float* W0     = (const float*)d_in[6];
    const float* b0     = (const float*)d_in[7];
    const float* W1     = (const float*)d_in[8];
    const float* b1     = (const float*)d_in[9];
    const float* W2     = (const float*)d_in[10];
    const float* b2     = (const float*)d_in[11];
    float* outg = (float*)d_out;

    const int B  = in_sizes[5];                       // P200c: [B]
    const int BT = in_sizes[2];                       // N: [B,T]
    const int T  = BT / B;
    const int ND = in_sizes[1] / (BT * 3);            // x: [B,T,ND,3]

    const int grid = (BT + NBT - 1) / NBT;
    netlocal_kernel<<<grid, 256>>>(x0g, xg, Ng, basisg, vg, Pg,
                                   W0, b0, W1, b1, W2, b2, outg, T, ND, BT);
}

// round 11
// speedup vs baseline: 1.1238x; 1.1238x over previous
#include <cuda_runtime.h>
#include <math.h>

#define EPSF 1e-5f
#define SPT_STR 256   // feature-major row stride (ND <= 256)

typedef unsigned long long ull;

// leaky_relu(z, 0.01) == 0.505*z + 0.495*|z|
__device__ __forceinline__ float lrelu(float z) {
    return fmaf(0.495f, fabsf(z), 0.505f * z);
}

// packed helpers (sm_103a f32x2 pipe)
#define FMA2(acc, a, b) \
    asm("fma.rn.f32x2 %0, %1, %2, %0;" : "+l"(acc) : "l"(a), "l"(b))
#define AND2(d, s, m) \
    asm("and.b64 %0, %1, %2;" : "=l"(d) : "l"(s), "l"(m))
#define PACK2(d, x) \
    asm("mov.b64 %0, {%1, %1};" : "=l"(d) : "r"(__float_as_uint(x)))
#define PACK2U(d, x) \
    asm("mov.b64 %0, {%1, %1};" : "=l"(d) : "r"(x))
#define UNPACK2(lo, hi, s) \
    asm("mov.b64 {%0, %1}, %2;" : "=r"(lo), "=r"(hi) : "l"(s))

__global__ __launch_bounds__(256) void netlocal_kernel(
    const float* __restrict__ x0g,   // [B,T,3]
    const float* __restrict__ xg,    // [B,T,ND,3]
    const int*   __restrict__ Ng,    // [B,T]
    const float* __restrict__ basisg,// [B,3,3]
    const float* __restrict__ vg,    // [B,T,ND,3]
    const float* __restrict__ Pg,    // [B]
    const float* __restrict__ W0,    // [19,127]
    const float* __restrict__ b0,    // [127]
    const float* __restrict__ W1,    // [128,128]
    const float* __restrict__ b1,    // [128]
    const float* __restrict__ W2,    // [128,128]
    const float* __restrict__ b2,    // [128]
    float*       __restrict__ outg,  // [B,T,128]
    int T, int ND)
{
    const int bt  = blockIdx.x;
    const int b   = bt / T;
    const int tid = threadIdx.x;

    __shared__ __align__(16) float spT[9 * SPT_STR];  // feature-major
    __shared__ float sbasis[9];
    __shared__ float fblk[10];
    __shared__ float sv0[3];
    __shared__ float wsum[8][3];
    __shared__ float zcs[128];        // per-column z-constant for MLP0
    __shared__ float poolp[128 * 5];  // [col][slice], stride 5 conflict-free
    __shared__ __align__(16) float sh[128];
    __shared__ __align__(16) float sh1[128];
    __shared__ __align__(16) float pDv[8][128];  // Phase-D split-k partials

    if (tid < 9) sbasis[tid] = basisg[b * 9 + tid];

    const float* vbase = vg + (size_t)bt * ND * 3;
    const float* xbase = xg + (size_t)bt * ND * 3;

    // ---- Phase A: v0 = mean over ND (deterministic tree reduction) ----
    float vx = 0.f, vy = 0.f, vz = 0.f;
    for (int n = tid; n < ND; n += 256) {
        vx += vbase[n * 3 + 0];
        vy += vbase[n * 3 + 1];
        vz += vbase[n * 3 + 2];
    }
#pragma unroll
    for (int o = 16; o > 0; o >>= 1) {
        vx += __shfl_xor_sync(0xffffffffu, vx, o);
        vy += __shfl_xor_sync(0xffffffffu, vy, o);
        vz += __shfl_xor_sync(0xffffffffu, vz, o);
    }
    if ((tid & 31) == 0) {
        wsum[tid >> 5][0] = vx;
        wsum[tid >> 5][1] = vy;
        wsum[tid >> 5][2] = vz;
    }
    __syncthreads();

    if (tid == 0) {
        float sx = 0.f, sy = 0.f, sz = 0.f;
#pragma unroll
        for (int w = 0; w < 8; w++) { sx += wsum[w][0]; sy += wsum[w][1]; sz += wsum[w][2]; }
        const float invN = 1.0f / (float)ND;
        const float v0x = sx * invN, v0y = sy * invN, v0z = sz * invN;
        sv0[0] = v0x; sv0[1] = v0y; sv0[2] = v0z;

        const float x00 = x0g[bt * 3 + 0], x01 = x0g[bt * 3 + 1], x02 = x0g[bt * 3 + 2];
        const float x0n = sqrtf(x00 * x00 + x01 * x01 + x02 * x02) + EPSF;
        const float ix  = 1.0f / x0n;
        const float x0ux = x00 * ix, x0uy = x01 * ix, x0uz = x02 * ix;

        const float v0n = sqrtf(v0x * v0x + v0y * v0y + v0z * v0z) + EPSF;
        const float iv  = 1.0f / v0n;
        const float v0ux = v0x * iv, v0uy = v0y * iv, v0uz = v0z * iv;

        fblk[0] = log1pf((float)Ng[bt]);                                   // f4
        fblk[1] = x0n;                                                     // f5
        fblk[2] = x0ux * sbasis[0] + x0uy * sbasis[1] + x0uz * sbasis[2];  // f6
        fblk[3] = x0ux * sbasis[3] + x0uy * sbasis[4] + x0uz * sbasis[5];  // f7
        fblk[4] = x0ux * sbasis[6] + x0uy * sbasis[7] + x0uz * sbasis[8];  // f8
        fblk[5] = v0n;                                                     // f9
        fblk[6] = v0ux * sbasis[0] + v0uy * sbasis[1] + v0uz * sbasis[2];  // f10
        fblk[7] = v0ux * sbasis[3] + v0uy * sbasis[4] + v0uz * sbasis[5];  // f11
        fblk[8] = v0ux * sbasis[6] + v0uy * sbasis[7] + v0uz * sbasis[8];  // f12
        fblk[9] = x0ux * v0ux + x0uy * v0uy + x0uz * v0uz;                 // f13
    }
    __syncthreads();

    // ---- Phase B: per-particle features into feature-major shared;
    //      plus zcs[j] computed once per column (tid<128) ----
    {
        const float v0x = sv0[0], v0y = sv0[1], v0z = sv0[2];
        const float bx0 = sbasis[0], bx1 = sbasis[1], bx2 = sbasis[2];
        const float by0 = sbasis[3], by1 = sbasis[4], by2 = sbasis[5];
        const float bz0 = sbasis[6], bz1 = sbasis[7], bz2 = sbasis[8];
        for (int n = tid; n < ND; n += 256) {
            const float ax = xbase[n * 3 + 0], ay = xbase[n * 3 + 1], az = xbase[n * 3 + 2];
            const float xn = sqrtf(ax * ax + ay * ay + az * az) + EPSF;
            const float ir = 1.0f / xn;
            const float xux = ax * ir, xuy = ay * ir, xuz = az * ir;

            const float wx = vbase[n * 3 + 0] - v0x;
            const float wy = vbase[n * 3 + 1] - v0y;
            const float wz = vbase[n * 3 + 2] - v0z;
            const float vn = sqrtf(wx * wx + wy * wy + wz * wz) + EPSF;
            const float ivn = 1.0f / vn;
            const float vux = wx * ivn, vuy = wy * ivn, vuz = wz * ivn;

            spT[0 * SPT_STR + n] = xn;
            spT[1 * SPT_STR + n] = xux * bx0 + xuy * bx1 + xuz * bx2;
            spT[2 * SPT_STR + n] = xux * by0 + xuy * by1 + xuz * by2;
            spT[3 * SPT_STR + n] = xux * bz0 + xuy * bz1 + xuz * bz2;
            spT[4 * SPT_STR + n] = vn;
            spT[5 * SPT_STR + n] = vux * bx0 + vuy * bx1 + vuz * bx2;
            spT[6 * SPT_STR + n] = vux * by0 + vuy * by1 + vuz * by2;
            spT[7 * SPT_STR + n] = vux * bz0 + vuy * bz1 + vuz * bz2;
            spT[8 * SPT_STR + n] = xux * vux + xuy * vuy + xuz * vuz;
        }
    }
    if (tid < 128) {
        float zv = 0.f;
        if (tid < 127) {
            zv = b0[tid];
#pragma unroll
            for (int i = 0; i < 10; i++)
                zv = fmaf(fblk[i], W0[(4 + i) * 127 + tid], zv);
        }
        zcs[tid] = zv;
    }
    __syncthreads();

    // ---- Phase C: MLP0 + mean pool, packed f32x2 (2 particles/lane-slot) ----
    // tid -> columns {j63, j63+64}, particle slice s4 = tid>>6 (warp-uniform).
    {
        const int j63 = tid & 63;
        const int s4  = tid >> 6;

        ull w2[2][9];
        ull zc2[2];
#pragma unroll
        for (int c = 0; c < 2; c++) {
            const int col = j63 + 64 * c;
            float wr[9];
            if (col < 127) {
                // per-particle feature rows of W0: {0,1,2,3,14,15,16,17,18}
                wr[0] = W0[0 * 127 + col];
                wr[1] = W0[1 * 127 + col];
                wr[2] = W0[2 * 127 + col];
                wr[3] = W0[3 * 127 + col];
                wr[4] = W0[14 * 127 + col];
                wr[5] = W0[15 * 127 + col];
                wr[6] = W0[16 * 127 + col];
                wr[7] = W0[17 * 127 + col];
                wr[8] = W0[18 * 127 + col];
            } else {
#pragma unroll
                for (int i = 0; i < 9; i++) wr[i] = 0.f;
            }
#pragma unroll
            for (int i = 0; i < 9; i++) PACK2(w2[c][i], wr[i]);
            PACK2(zc2[c], zcs[col]);
        }

        ull c505, c495, mabs;
        PACK2(c505, 0.505f);
        PACK2(c495, 0.495f);
        PACK2U(mabs, 0x7FFFFFFFu);

        const int nspl = ND >> 2;       // particles per slice
        const int n0b  = s4 * nspl;
        ull acc[2][2] = {{0ull, 0ull}, {0ull, 0ull}};

        for (int i = 0; i < nspl; i += 4) {
            const int n0 = n0b + i;
            ull z00 = zc2[0], z01 = zc2[0], z10 = zc2[1], z11 = zc2[1];
#pragma unroll
            for (int k = 0; k < 9; k++) {
                const ulonglong2 qv =
                    *(const ulonglong2*)(spT + k * SPT_STR + n0);
                FMA2(z00, w2[0][k], qv.x);
                FMA2(z01, w2[0][k], qv.y);
                FMA2(z10, w2[1][k], qv.x);
                FMA2(z11, w2[1][k], qv.y);
            }
            ull a;
            AND2(a, z00, mabs); FMA2(acc[0][0], c505, z00); FMA2(acc[0][0], c495, a);
            AND2(a, z01, mabs); FMA2(acc[0][1], c505, z01); FMA2(acc[0][1], c495, a);
            AND2(a, z10, mabs); FMA2(acc[1][0], c505, z10); FMA2(acc[1][0], c495, a);
            AND2(a, z11, mabs); FMA2(acc[1][1], c505, z11); FMA2(acc[1][1], c495, a);
        }

#pragma unroll
        for (int c = 0; c < 2; c++) {
            unsigned int l0, h0, l1, h1;
            UNPACK2(l0, h0, acc[c][0]);
            UNPACK2(l1, h1, acc[c][1]);
            const float tot = (__uint_as_float(l0) + __uint_as_float(h0)) +
                              (__uint_as_float(l1) + __uint_as_float(h1));
            poolp[(j63 + 64 * c) * 5 + s4] = tot;
        }
    }
    __syncthreads();

    if (tid < 128) {
        float sm = 0.f;
#pragma unroll
        for (int w = 0; w < 4; w++) sm += poolp[tid * 5 + w];
        const float pm = sm * (1.0f / (float)ND);
        sh[tid] = (tid < 127) ? pm : fblk[0];   // append log1p(N) at index 127
    }
    __syncthreads();

    // ---- Phase D: vectorized matvecs. thread -> 4 cols, 8-way split-k ----
    const int c4 = (tid & 31) * 4;
    const int s8 = tid >> 5;
    {
        ull alo = 0ull, ahi = 0ull;
        const int k0 = s8 * 16;
#pragma unroll 4
        for (int k = k0; k < k0 + 16; k++) {
            const ulonglong2 wq = *(const ulonglong2*)(W1 + k * 128 + c4);
            ull h2; PACK2(h2, sh[k]);
            FMA2(alo, wq.x, h2);
            FMA2(ahi, wq.y, h2);
        }
        *(ulonglong2*)&pDv[s8][c4] = make_ulonglong2(alo, ahi);
    }
    __syncthreads();
    if (tid < 128) {
        float a1 = b1[tid];
#pragma unroll
        for (int s = 0; s < 8; s++) a1 += pDv[s][tid];
        sh1[tid] = lrelu(a1);
    }
    __syncthreads();
    {
        ull alo = 0ull, ahi = 0ull;
        const int k0 = s8 * 16;
#pragma unroll 4
        for (int k = k0; k < k0 + 16; k++) {
            const ulonglong2 wq = *(const ulonglong2*)(W2 + k * 128 + c4);
            ull h2; PACK2(h2, sh1[k]);
            FMA2(alo, wq.x, h2);
            FMA2(ahi, wq.y, h2);
        }
        *(ulonglong2*)&pDv[s8][c4] = make_ulonglong2(alo, ahi);
    }
    __syncthreads();
    if (tid < 128) {
        float a2 = b2[tid];
#pragma unroll
        for (int s = 0; s < 8; s++) a2 += pDv[s][tid];
        outg[(size_t)bt * 128 + tid] = a2 * (1.0f / Pg[b]);
    }
}

extern "C" void kernel_launch(void* const* d_in, const int* in_sizes, int n_in,
                              void* d_out, int out_size) {
    const float* x0g    = (const float*)d_in[0];
    const float* xg     = (const float*)d_in[1];
    const int*   Ng     = (const int*)  d_in[2];
    const float* basisg = (const float*)d_in[3];
    const float* vg     = (const float*)d_in[4];
    const float* Pg     = (const float*)d_in[5];
    const float* W0     = (const float*)d_in[6];
    const float* b0     = (const float*)d_in[7];
    const float* W1     = (const float*)d_in[8];
    const float* b1     = (const float*)d_in[9];
    const float* W2     = (const float*)d_in[10];
    const float* b2     = (const float*)d_in[11];
    float* outg = (float*)d_out;

    const int B  = in_sizes[5];                       // P200c: [B]
    const int BT = in_sizes[2];                       // N: [B,T]
    const int T  = BT / B;
    const int ND = in_sizes[1] / (BT * 3);            // x: [B,T,ND,3]

    netlocal_kernel<<<BT, 256>>>(x0g, xg, Ng, basisg, vg, Pg,
                                 W0, b0, W1, b1, W2, b2, outg, T, ND);
}

// round 12
// speedup vs baseline: 1.2132x; 1.0795x over previous
#include <cuda_runtime.h>
#include <math.h>

#define EPSF 1e-5f
#define SPT_STR 256   // feature-major row stride (ND <= 256)

typedef unsigned long long ull;

// leaky_relu(z, 0.01) == 0.505*z + 0.495*|z|
__device__ __forceinline__ float lrelu(float z) {
    return fmaf(0.495f, fabsf(z), 0.505f * z);
}

// packed helpers (sm_103a f32x2 pipe)
#define FMA2(acc, a, b) \
    asm("fma.rn.f32x2 %0, %1, %2, %0;" : "+l"(acc) : "l"(a), "l"(b))
#define AND2(d, s, m) \
    asm("and.b64 %0, %1, %2;" : "=l"(d) : "l"(s), "l"(m))
#define PACK2(d, x) \
    asm("mov.b64 %0, {%1, %1};" : "=l"(d) : "r"(__float_as_uint(x)))
#define PACK2U(d, x) \
    asm("mov.b64 %0, {%1, %1};" : "=l"(d) : "r"(x))
#define UNPACK2(lo, hi, s) \
    asm("mov.b64 {%0, %1}, %2;" : "=r"(lo), "=r"(hi) : "l"(s))

__global__ __launch_bounds__(256, 4) void netlocal_kernel(
    const float* __restrict__ x0g,   // [B,T,3]
    const float* __restrict__ xg,    // [B,T,ND,3]
    const int*   __restrict__ Ng,    // [B,T]
    const float* __restrict__ basisg,// [B,3,3]
    const float* __restrict__ vg,    // [B,T,ND,3]
    const float* __restrict__ Pg,    // [B]
    const float* __restrict__ W0,    // [19,127]
    const float* __restrict__ b0,    // [127]
    const float* __restrict__ W1,    // [128,128]
    const float* __restrict__ b1,    // [128]
    const float* __restrict__ W2,    // [128,128]
    const float* __restrict__ b2,    // [128]
    float*       __restrict__ outg,  // [B,T,128]
    int T, int ND)
{
    const int bt  = blockIdx.x;
    const int b   = bt / T;
    const int tid = threadIdx.x;

    __shared__ __align__(16) float spT[9 * SPT_STR];  // feature-major
    __shared__ float fblk[10];
    __shared__ float sv0[3];
    __shared__ float wsum[8][3];
    __shared__ float zcs[128];        // per-column z-constant for MLP0
    __shared__ float poolp[128 * 5];  // [col][slice], stride 5 conflict-free
    __shared__ __align__(16) float sh[128];
    __shared__ __align__(16) float sh1[128];
    __shared__ __align__(16) float pDv[8][128];  // Phase-D split-k partials

    const float* bas   = basisg + b * 9;   // uniform-address, L1-resident
    const float* vbase = vg + (size_t)bt * ND * 3;
    const float* xbase = xg + (size_t)bt * ND * 3;

    // ---- Phase A: one particle per thread (ND <= 256). Load x and v ONCE,
    //      compute x-features now (independent of v0), cache xu and v. ----
    float xux = 0.f, xuy = 0.f, xuz = 0.f;   // cached unit x
    float vpx = 0.f, vpy = 0.f, vpz = 0.f;   // cached raw v
    {
        float vx = 0.f, vy = 0.f, vz = 0.f;
        if (tid < ND) {
            const float ax = xbase[tid * 3 + 0];
            const float ay = xbase[tid * 3 + 1];
            const float az = xbase[tid * 3 + 2];
            vpx = vbase[tid * 3 + 0];
            vpy = vbase[tid * 3 + 1];
            vpz = vbase[tid * 3 + 2];
            vx = vpx; vy = vpy; vz = vpz;

            const float xn = sqrtf(ax * ax + ay * ay + az * az) + EPSF;
            const float ir = 1.0f / xn;
            xux = ax * ir; xuy = ay * ir; xuz = az * ir;

            spT[0 * SPT_STR + tid] = xn;
            spT[1 * SPT_STR + tid] = xux * bas[0] + xuy * bas[1] + xuz * bas[2];
            spT[2 * SPT_STR + tid] = xux * bas[3] + xuy * bas[4] + xuz * bas[5];
            spT[3 * SPT_STR + tid] = xux * bas[6] + xuy * bas[7] + xuz * bas[8];
        }
        // deterministic tree reduction of v
#pragma unroll
        for (int o = 16; o > 0; o >>= 1) {
            vx += __shfl_xor_sync(0xffffffffu, vx, o);
            vy += __shfl_xor_sync(0xffffffffu, vy, o);
            vz += __shfl_xor_sync(0xffffffffu, vz, o);
        }
        if ((tid & 31) == 0) {
            wsum[tid >> 5][0] = vx;
            wsum[tid >> 5][1] = vy;
            wsum[tid >> 5][2] = vz;
        }
    }
    __syncthreads();

    if (tid == 0) {
        float sx = 0.f, sy = 0.f, sz = 0.f;
#pragma unroll
        for (int w = 0; w < 8; w++) { sx += wsum[w][0]; sy += wsum[w][1]; sz += wsum[w][2]; }
        const float invN = 1.0f / (float)ND;
        const float v0x = sx * invN, v0y = sy * invN, v0z = sz * invN;
        sv0[0] = v0x; sv0[1] = v0y; sv0[2] = v0z;

        const float x00 = x0g[bt * 3 + 0], x01 = x0g[bt * 3 + 1], x02 = x0g[bt * 3 + 2];
        const float x0n = sqrtf(x00 * x00 + x01 * x01 + x02 * x02) + EPSF;
        const float ix  = 1.0f / x0n;
        const float x0ux = x00 * ix, x0uy = x01 * ix, x0uz = x02 * ix;

        const float v0n = sqrtf(v0x * v0x + v0y * v0y + v0z * v0z) + EPSF;
        const float iv  = 1.0f / v0n;
        const float v0ux = v0x * iv, v0uy = v0y * iv, v0uz = v0z * iv;

        fblk[0] = log1pf((float)Ng[bt]);                             // f4
        fblk[1] = x0n;                                               // f5
        fblk[2] = x0ux * bas[0] + x0uy * bas[1] + x0uz * bas[2];     // f6
        fblk[3] = x0ux * bas[3] + x0uy * bas[4] + x0uz * bas[5];     // f7
        fblk[4] = x0ux * bas[6] + x0uy * bas[7] + x0uz * bas[8];     // f8
        fblk[5] = v0n;                                               // f9
        fblk[6] = v0ux * bas[0] + v0uy * bas[1] + v0uz * bas[2];     // f10
        fblk[7] = v0ux * bas[3] + v0uy * bas[4] + v0uz * bas[5];     // f11
        fblk[8] = v0ux * bas[6] + v0uy * bas[7] + v0uz * bas[8];     // f12
        fblk[9] = x0ux * v0ux + x0uy * v0uy + x0uz * v0uz;           // f13
    }
    __syncthreads();

    // ---- Phase B: v-features from cached registers (no global reloads);
    //      zcs[j] once per column (tid<128) ----
    if (tid < ND) {
        const float wx = vpx - sv0[0];
        const float wy = vpy - sv0[1];
        const float wz = vpz - sv0[2];
        const float vn = sqrtf(wx * wx + wy * wy + wz * wz) + EPSF;
        const float ivn = 1.0f / vn;
        const float vux = wx * ivn, vuy = wy * ivn, vuz = wz * ivn;

        spT[4 * SPT_STR + tid] = vn;
        spT[5 * SPT_STR + tid] = vux * bas[0] + vuy * bas[1] + vuz * bas[2];
        spT[6 * SPT_STR + tid] = vux * bas[3] + vuy * bas[4] + vuz * bas[5];
        spT[7 * SPT_STR + tid] = vux * bas[6] + vuy * bas[7] + vuz * bas[8];
        spT[8 * SPT_STR + tid] = xux * vux + xuy * vuy + xuz * vuz;
    }
    if (tid < 128) {
        float zv = 0.f;
        if (tid < 127) {
            zv = b0[tid];
#pragma unroll
            for (int i = 0; i < 10; i++)
                zv = fmaf(fblk[i], W0[(4 + i) * 127 + tid], zv);
        }
        zcs[tid] = zv;
    }
    __syncthreads();

    // ---- Phase C: MLP0 + mean pool, packed f32x2 (2 particles/lane-slot) ----
    // tid -> columns {j63, j63+64}, particle slice s4 = tid>>6 (warp-uniform).
    {
        const int j63 = tid & 63;
        const int s4  = tid >> 6;

        ull w2[2][9];
        ull zc2[2];
#pragma unroll
        for (int c = 0; c < 2; c++) {
            const int col = j63 + 64 * c;
            float wr[9];
            if (col < 127) {
                // per-particle feature rows of W0: {0,1,2,3,14,15,16,17,18}
                wr[0] = W0[0 * 127 + col];
                wr[1] = W0[1 * 127 + col];
                wr[2] = W0[2 * 127 + col];
                wr[3] = W0[3 * 127 + col];
                wr[4] = W0[14 * 127 + col];
                wr[5] = W0[15 * 127 + col];
                wr[6] = W0[16 * 127 + col];
                wr[7] = W0[17 * 127 + col];
                wr[8] = W0[18 * 127 + col];
            } else {
#pragma unroll
                for (int i = 0; i < 9; i++) wr[i] = 0.f;
            }
#pragma unroll
            for (int i = 0; i < 9; i++) PACK2(w2[c][i], wr[i]);
            PACK2(zc2[c], zcs[col]);
        }

        ull c505, c495, mabs;
        PACK2(c505, 0.505f);
        PACK2(c495, 0.495f);
        PACK2U(mabs, 0x7FFFFFFFu);

        const int nspl = ND >> 2;       // particles per slice
        const int n0b  = s4 * nspl;
        ull acc[2][2] = {{0ull, 0ull}, {0ull, 0ull}};

        for (int i = 0; i < nspl; i += 4) {
            const int n0 = n0b + i;
            ull z00 = zc2[0], z01 = zc2[0], z10 = zc2[1], z11 = zc2[1];
#pragma unroll
            for (int k = 0; k < 9; k++) {
                const ulonglong2 qv =
                    *(const ulonglong2*)(spT + k * SPT_STR + n0);
                FMA2(z00, w2[0][k], qv.x);
                FMA2(z01, w2[0][k], qv.y);
                FMA2(z10, w2[1][k], qv.x);
                FMA2(z11, w2[1][k], qv.y);
            }
            ull a;
            AND2(a, z00, mabs); FMA2(acc[0][0], c505, z00); FMA2(acc[0][0], c495, a);
            AND2(a, z01, mabs); FMA2(acc[0][1], c505, z01); FMA2(acc[0][1], c495, a);
            AND2(a, z10, mabs); FMA2(acc[1][0], c505, z10); FMA2(acc[1][0], c495, a);
            AND2(a, z11, mabs); FMA2(acc[1][1], c505, z11); FMA2(acc[1][1], c495, a);
        }

#pragma unroll
        for (int c = 0; c < 2; c++) {
            unsigned int l0, h0, l1, h1;
            UNPACK2(l0, h0, acc[c][0]);
            UNPACK2(l1, h1, acc[c][1]);
            const float tot = (__uint_as_float(l0) + __uint_as_float(h0)) +
                              (__uint_as_float(l1) + __uint_as_float(h1));
            poolp[(j63 + 64 * c) * 5 + s4] = tot;
        }
    }
    __syncthreads();

    if (tid < 128) {
        float sm = 0.f;
#pragma unroll
        for (int w = 0; w < 4; w++) sm += poolp[tid * 5 + w];
        const float pm = sm * (1.0f / (float)ND);
        sh[tid] = (tid < 127) ? pm : fblk[0];   // append log1p(N) at index 127
    }
    __syncthreads();

    // ---- Phase D: vectorized matvecs. thread -> 4 cols, 8-way split-k ----
    const int c4 = (tid & 31) * 4;
    const int s8 = tid >> 5;
    {
        ull alo = 0ull, ahi = 0ull;
        const int k0 = s8 * 16;
#pragma unroll 4
        for (int k = k0; k < k0 + 16; k++) {
            const ulonglong2 wq = *(const ulonglong2*)(W1 + k * 128 + c4);
            ull h2; PACK2(h2, sh[k]);
            FMA2(alo, wq.x, h2);
            FMA2(ahi, wq.y, h2);
        }
        *(ulonglong2*)&pDv[s8][c4] = make_ulonglong2(alo, ahi);
    }
    __syncthreads();
    if (tid < 128) {
        float a1 = b1[tid];
#pragma unroll
        for (int s = 0; s < 8; s++) a1 += pDv[s][tid];
        sh1[tid] = lrelu(a1);
    }
    __syncthreads();
    {
        ull alo = 0ull, ahi = 0ull;
        const int k0 = s8 * 16;
#pragma unroll 4
        for (int k = k0; k < k0 + 16; k++) {
            const ulonglong2 wq = *(const ulonglong2*)(W2 + k * 128 + c4);
            ull h2; PACK2(h2, sh1[k]);
            FMA2(alo, wq.x, h2);
            FMA2(ahi, wq.y, h2);
        }
        *(ulonglong2*)&pDv[s8][c4] = make_ulonglong2(alo, ahi);
    }
    __syncthreads();
    if (tid < 128) {
        float a2 = b2[tid];
#pragma unroll
        for (int s = 0; s < 8; s++) a2 += pDv[s][tid];
        outg[(size_t)bt * 128 + tid] = a2 * (1.0f / Pg[b]);
    }
}

extern "C" void kernel_launch(void* const* d_in, const int* in_sizes, int n_in,
                              void* d_out, int out_size) {
    const float* x0g    = (const float*)d_in[0];
    const float* xg     = (const float*)d_in[1];
    const int*   Ng     = (const int*)  d_in[2];
    const float* basisg = (const float*)d_in[3];
    const float* vg     = (const float*)d_in[4];
    const float* Pg     = (const float*)d_in[5];
    const float* W0     = (const float*)d_in[6];
    const float* b0     = (const float*)d_in[7];
    const float* W1     = (const float*)d_in[8];
    const float* b1     = (const float*)d_in[9];
    const float* W2     = (const float*)d_in[10];
    const float* b2     = (const float*)d_in[11];
    float* outg = (float*)d_out;

    const int B  = in_sizes[5];                       // P200c: [B]
    const int BT = in_sizes[2];                       // N: [B,T]
    const int T  = BT / B;
    const int ND = in_sizes[1] / (BT * 3);            // x: [B,T,ND,3]

    netlocal_kernel<<<BT, 256>>>(x0g, xg, Ng, basisg, vg, Pg,
                                 W0, b0, W1, b1, W2, b2, outg, T, ND);
}